// round 12
// baseline (speedup 1.0000x reference)
#include <cuda_runtime.h>
#include <cstdint>
#include <cmath>

// ---------------------------------------------------------------------------
// SpecAugment: out = where(freq_mask[b,f] | time_mask[b,t], 0, x)
// FINAL (R8 configuration — best measured total, 45.15us):
// Host computes the 1280 threefry draws (bit-exact jax_threefry_partitionable,
// verified rel_err=0.0 every round), passed as __grid_constant__.
// Device: ONE ROW PER 128-THREAD BLOCK (fine-grained => HW work-steal
// balances freq-masked store-only rows against full rows), 8 float4 loads
// per thread front-batched (MLP_p1=8) with fully-masked loads skipped,
// streaming (__ldcs/__stcs) memory ops.
// Plateau analysis: kernel ~38us @ ~5.6TB/s = DRAM mixed-stream ceiling for
// 164MB writes + ~50MB live reads; all scheduling/vector/cache levers probed.
// ---------------------------------------------------------------------------

#define B_DIM 128
#define F_DIM 80
#define T_DIM 4000
#define T4    1000          // float4 per row
#define TW    125           // 32-bit time-mask words per batch
#define NTHREADS 128
#define VEC 8               // float4 per thread (128 * 8 = 1024 >= 1000)

struct MaskParams {
    uint32_t frow[(B_DIM * F_DIM + 31) / 32];  // bit per (b,f) row
    short ts[B_DIM * 10];                      // time band start
    short te[B_DIM * 10];                      // time band end (exclusive)
};

// ============================ device ======================================

__global__ void __launch_bounds__(NTHREADS)
apply_kernel(const float4* __restrict__ x, float4* __restrict__ out,
             const __grid_constant__ MaskParams p)
{
    const int row = blockIdx.x;                // row = b*80 + f (contiguous)
    const int b   = row / F_DIM;
    const int tid = threadIdx.x;

    const float4* xr   = x   + (size_t)row * T4;
    float4*       orow = out + (size_t)row * T4;
    const float4  z    = make_float4(0.f, 0.f, 0.f, 0.f);

    // Freq-masked row: store zeros, read nothing, exit fast (work-steal
    // backfills this SM slot with another block).
    if ((p.frow[row >> 5] >> (row & 31)) & 1u) {
#pragma unroll
        for (int i = 0; i < VEC; i++) {
            int t4 = tid + i * NTHREADS;
            if (t4 < T4) __stcs(orow + t4, z);
        }
        return;
    }

    // Build this batch's packed time mask in shared (125 words, 10 bands).
    __shared__ uint32_t s_tb[TW];
    if (tid < TW) {
        const int base = tid * 32;
        uint32_t word = 0u;
#pragma unroll
        for (int m = 0; m < 10; m++) {
            int s = p.ts[b * 10 + m], e = p.te[b * 10 + m];
            int lo = s - base;  lo = lo < 0  ? 0  : lo;
            int hi = e - base;  hi = hi > 32 ? 32 : hi;
            if (hi > lo) {
                uint32_t mhi = (hi >= 32) ? 0xFFFFFFFFu : ((1u << hi) - 1u);
                word |= mhi & ~((1u << lo) - 1u);
            }
        }
        s_tb[tid] = word;
    }
    __syncthreads();

    // Per-t4 nibbles (4 mask bits per float4).
    uint32_t nib[VEC];
#pragma unroll
    for (int i = 0; i < VEC; i++) {
        int t4 = tid + i * NTHREADS;
        nib[i] = (t4 < T4) ? ((s_tb[t4 >> 3] >> ((t4 & 7) * 4)) & 0xFu) : 0xFu;
    }

    // ALL loads front-batched (up to 8 outstanding); fully-masked skipped.
    float4 v[VEC];
#pragma unroll
    for (int i = 0; i < VEC; i++) {
        int t4 = tid + i * NTHREADS;
        v[i] = z;
        if (t4 < T4 && nib[i] != 0xFu) v[i] = __ldcs(xr + t4);
    }

    // Streaming stores.
#pragma unroll
    for (int i = 0; i < VEC; i++) {
        int t4 = tid + i * NTHREADS;
        if (t4 >= T4) continue;
        float4 o = v[i];
        o.x = (nib[i] & 1u) ? 0.f : o.x;
        o.y = (nib[i] & 2u) ? 0.f : o.y;
        o.z = (nib[i] & 4u) ? 0.f : o.z;
        o.w = (nib[i] & 8u) ? 0.f : o.w;
        __stcs(orow + t4, o);
    }
}

// ============================ host: threefry draws ========================

namespace sa_host {

struct U2 { uint32_t a, b; };

static inline U2 tf(uint32_t k0, uint32_t k1, uint32_t x0, uint32_t x1) {
    const uint32_t ks2 = k0 ^ k1 ^ 0x1BD11BDAu;
    x0 += k0; x1 += k1;
#define RND(r) { x0 += x1; x1 = (x1 << (r)) | (x1 >> (32 - (r))); x1 ^= x0; }
    RND(13) RND(15) RND(26) RND(6)
    x0 += k1;  x1 += ks2 + 1u;
    RND(17) RND(29) RND(16) RND(24)
    x0 += ks2; x1 += k0 + 2u;
    RND(13) RND(15) RND(26) RND(6)
    x0 += k0;  x1 += k1 + 3u;
    RND(17) RND(29) RND(16) RND(24)
    x0 += k1;  x1 += ks2 + 4u;
    RND(13) RND(15) RND(26) RND(6)
    x0 += ks2; x1 += k0 + 5u;
#undef RND
    return U2{x0, x1};
}

// jax_threefry_partitionable = True (verified bit-exact)
static inline U2 split_a(U2 k) { return tf(k.a, k.b, 0u, 0u); }
static inline U2 split_b(U2 k) { return tf(k.a, k.b, 0u, 1u); }
static inline uint32_t rbits(U2 k, uint32_t j) {
    U2 o = tf(k.a, k.b, 0u, j);
    return o.a ^ o.b;
}

static void fill_params(MaskParams& p) {
    U2 key{0u, 42u};                       // jax.random.key(42)
    U2 kf  = split_a(key), kt  = split_b(key);
    U2 kwf = split_a(kf),  ksf = split_b(kf);
    U2 kwt = split_a(kt),  kst = split_b(kt);
    U2 k1f = split_a(kwf), k2f = split_b(kwf);
    U2 k1t = split_a(kwt), k2t = split_b(kwt);

    // Freq: (128, 2) draws, span 28, multiplier 2^32 % 28 = 4
    int fs[B_DIM * 2], fe[B_DIM * 2];
    for (int j = 0; j < B_DIM * 2; j++) {
        uint32_t h  = rbits(k1f, (uint32_t)j);
        uint32_t l  = rbits(k2f, (uint32_t)j);
        uint32_t ub = rbits(ksf, (uint32_t)j);
        uint32_t w  = ((h % 28u) * 4u + (l % 28u)) % 28u;
        float u  = (float)(ub >> 9) * (1.0f / 8388608.0f);  // exact [0,1)
        int hi   = F_DIM - (int)w;                          // max(1,80-w), w<=27
        int s    = (int)(u * (float)hi);
        fs[j] = s; fe[j] = s + (int)w;
    }
    for (int i = 0; i < (int)(sizeof(p.frow) / sizeof(p.frow[0])); i++) p.frow[i] = 0u;
    for (int b = 0; b < B_DIM; b++)
        for (int f = 0; f < F_DIM; f++) {
            bool in = (f >= fs[2 * b]     && f < fe[2 * b]) ||
                      (f >= fs[2 * b + 1] && f < fe[2 * b + 1]);
            if (in) {
                int r = b * F_DIM + f;
                p.frow[r >> 5] |= 1u << (r & 31);
            }
        }

    // Time: (128, 10) draws, span 101, multiplier 2^32 % 101 = 68
    for (int j = 0; j < B_DIM * 10; j++) {
        uint32_t h  = rbits(k1t, (uint32_t)j);
        uint32_t l  = rbits(k2t, (uint32_t)j);
        uint32_t ub = rbits(kst, (uint32_t)j);
        uint32_t w  = ((h % 101u) * 68u + (l % 101u)) % 101u;
        float u  = (float)(ub >> 9) * (1.0f / 8388608.0f);
        int hi   = T_DIM - (int)w;                          // max(1,4000-w), w<=100
        int s    = (int)(u * (float)hi);
        p.ts[j] = (short)s;
        p.te[j] = (short)(s + (int)w);
    }
}

} // namespace sa_host

// ============================ launch ======================================

extern "C" void kernel_launch(void* const* d_in, const int* in_sizes, int n_in,
                              void* d_out, int out_size) {
    (void)in_sizes; (void)n_in; (void)out_size;
    const float4* x   = (const float4*)d_in[0];
    float4*       out = (float4*)d_out;

    MaskParams p;
    sa_host::fill_params(p);

    apply_kernel<<<B_DIM * F_DIM, NTHREADS>>>(x, out, p);
}

// round 13
// speedup vs baseline: 1.0063x; 1.0063x over previous
#include <cuda_runtime.h>
#include <cstdint>
#include <cmath>

// ---------------------------------------------------------------------------
// SpecAugment: out = where(freq_mask[b,f] | time_mask[b,t], 0, x)
// FINAL: host computes the 1280 threefry draws (bit-exact jax_threefry_
// partitionable, rel_err=0.0 across 11 benches), passed as a compact 5.1KB
// __grid_constant__ param. Device: one row per 128-thread block (fine-grained
// => HW work-steal balances store-only freq-masked rows), Blackwell 256-bit
// vector ops (ld/st.global.v8.f32 -> LDG.256/STG.256): 4 x 32B chunks per
// thread, front-batched, loads skipped where fully masked. Best measured
// kernel of the series: 37.8us @ 5.70TB/s (DRAM mixed-stream ceiling).
// ---------------------------------------------------------------------------

#define B_DIM 128
#define F_DIM 80
#define T_DIM 4000
#define T8    500           // 32B (8-float) chunks per row
#define TW    125           // 32-bit time-mask words per batch
#define NTHREADS 128
#define VEC 4               // chunks per thread (128 * 4 = 512 >= 500)

struct MaskParams {
    uint32_t frow[(B_DIM * F_DIM + 31) / 32];  // 1280B: bit per (b,f) row
    short    ts[B_DIM * 10];                   // 2560B: time band start
    uint8_t  tw[B_DIM * 10];                   // 1280B: time band width (<=100)
};

// ====================== 256-bit memory ops (sm_100a+) =====================

__device__ __forceinline__ void ld256_cs(const float* p, float* v) {
    asm volatile("ld.global.cs.v8.f32 {%0,%1,%2,%3,%4,%5,%6,%7}, [%8];"
        : "=f"(v[0]), "=f"(v[1]), "=f"(v[2]), "=f"(v[3]),
          "=f"(v[4]), "=f"(v[5]), "=f"(v[6]), "=f"(v[7])
        : "l"(p));
}

__device__ __forceinline__ void st256_cs(float* p, const float* v) {
    asm volatile("st.global.cs.v8.f32 [%0], {%1,%2,%3,%4,%5,%6,%7,%8};"
        :: "l"(p),
           "f"(v[0]), "f"(v[1]), "f"(v[2]), "f"(v[3]),
           "f"(v[4]), "f"(v[5]), "f"(v[6]), "f"(v[7])
        : "memory");
}

// ============================ device ======================================

__global__ void __launch_bounds__(NTHREADS)
apply_kernel(const float* __restrict__ x, float* __restrict__ out,
             const __grid_constant__ MaskParams p)
{
    const int row = blockIdx.x;                // row = b*80 + f (contiguous)
    const int b   = row / F_DIM;
    const int tid = threadIdx.x;

    const float* xr   = x   + (size_t)row * T_DIM;
    float*       orow = out + (size_t)row * T_DIM;

    float zv[8] = {0.f, 0.f, 0.f, 0.f, 0.f, 0.f, 0.f, 0.f};

    // Freq-masked row: store zeros, read nothing, exit fast (work-steal
    // backfills this SM slot with another block).
    if ((p.frow[row >> 5] >> (row & 31)) & 1u) {
#pragma unroll
        for (int i = 0; i < VEC; i++) {
            int t8 = tid + i * NTHREADS;
            if (t8 < T8) st256_cs(orow + t8 * 8, zv);
        }
        return;
    }

    // Build this batch's packed time mask in shared (125 words, 10 bands).
    __shared__ uint32_t s_tb[TW];
    if (tid < TW) {
        const int base = tid * 32;
        uint32_t word = 0u;
#pragma unroll
        for (int m = 0; m < 10; m++) {
            int s = p.ts[b * 10 + m];
            int e = s + (int)p.tw[b * 10 + m];
            int lo = s - base;  lo = lo < 0  ? 0  : lo;
            int hi = e - base;  hi = hi > 32 ? 32 : hi;
            if (hi > lo) {
                uint32_t mhi = (hi >= 32) ? 0xFFFFFFFFu : ((1u << hi) - 1u);
                word |= mhi & ~((1u << lo) - 1u);
            }
        }
        s_tb[tid] = word;
    }
    __syncthreads();

    // Per-chunk mask bytes: chunk t8 covers t in [8*t8, 8*t8+8) = byte
    // (t8 & 3) of time-mask word (t8 >> 2).
    uint32_t mb[VEC];
#pragma unroll
    for (int i = 0; i < VEC; i++) {
        int t8 = tid + i * NTHREADS;
        mb[i] = (t8 < T8) ? ((s_tb[t8 >> 2] >> ((t8 & 3) * 8)) & 0xFFu) : 0xFFu;
    }

    // ALL 256-bit loads front-batched; fully-masked chunks skipped.
    float v[VEC][8];
#pragma unroll
    for (int i = 0; i < VEC; i++) {
#pragma unroll
        for (int jj = 0; jj < 8; jj++) v[i][jj] = 0.f;
        int t8 = tid + i * NTHREADS;
        if (t8 < T8 && mb[i] != 0xFFu) ld256_cs(xr + t8 * 8, v[i]);
    }

    // Mask + 256-bit streaming stores.
#pragma unroll
    for (int i = 0; i < VEC; i++) {
        int t8 = tid + i * NTHREADS;
        if (t8 >= T8) continue;
#pragma unroll
        for (int jj = 0; jj < 8; jj++)
            v[i][jj] = ((mb[i] >> jj) & 1u) ? 0.f : v[i][jj];
        st256_cs(orow + t8 * 8, v[i]);
    }
}

// ============================ host: threefry draws ========================

namespace sa_host {

struct U2 { uint32_t a, b; };

static inline U2 tf(uint32_t k0, uint32_t k1, uint32_t x0, uint32_t x1) {
    const uint32_t ks2 = k0 ^ k1 ^ 0x1BD11BDAu;
    x0 += k0; x1 += k1;
#define RND(r) { x0 += x1; x1 = (x1 << (r)) | (x1 >> (32 - (r))); x1 ^= x0; }
    RND(13) RND(15) RND(26) RND(6)
    x0 += k1;  x1 += ks2 + 1u;
    RND(17) RND(29) RND(16) RND(24)
    x0 += ks2; x1 += k0 + 2u;
    RND(13) RND(15) RND(26) RND(6)
    x0 += k0;  x1 += k1 + 3u;
    RND(17) RND(29) RND(16) RND(24)
    x0 += k1;  x1 += ks2 + 4u;
    RND(13) RND(15) RND(26) RND(6)
    x0 += ks2; x1 += k0 + 5u;
#undef RND
    return U2{x0, x1};
}

// jax_threefry_partitionable = True (verified bit-exact)
static inline U2 split_a(U2 k) { return tf(k.a, k.b, 0u, 0u); }
static inline U2 split_b(U2 k) { return tf(k.a, k.b, 0u, 1u); }
static inline uint32_t rbits(U2 k, uint32_t j) {
    U2 o = tf(k.a, k.b, 0u, j);
    return o.a ^ o.b;
}

static void fill_params(MaskParams& p) {
    U2 key{0u, 42u};                       // jax.random.key(42)
    U2 kf  = split_a(key), kt  = split_b(key);
    U2 kwf = split_a(kf),  ksf = split_b(kf);
    U2 kwt = split_a(kt),  kst = split_b(kt);
    U2 k1f = split_a(kwf), k2f = split_b(kwf);
    U2 k1t = split_a(kwt), k2t = split_b(kwt);

    // Freq: (128, 2) draws, span 28, multiplier 2^32 % 28 = 4
    int fs[B_DIM * 2], fe[B_DIM * 2];
    for (int j = 0; j < B_DIM * 2; j++) {
        uint32_t h  = rbits(k1f, (uint32_t)j);
        uint32_t l  = rbits(k2f, (uint32_t)j);
        uint32_t ub = rbits(ksf, (uint32_t)j);
        uint32_t w  = ((h % 28u) * 4u + (l % 28u)) % 28u;
        float u  = (float)(ub >> 9) * (1.0f / 8388608.0f);  // exact [0,1)
        int hi   = F_DIM - (int)w;                          // max(1,80-w), w<=27
        int s    = (int)(u * (float)hi);
        fs[j] = s; fe[j] = s + (int)w;
    }
    for (int i = 0; i < (int)(sizeof(p.frow) / sizeof(p.frow[0])); i++) p.frow[i] = 0u;
    for (int b = 0; b < B_DIM; b++)
        for (int f = 0; f < F_DIM; f++) {
            bool in = (f >= fs[2 * b]     && f < fe[2 * b]) ||
                      (f >= fs[2 * b + 1] && f < fe[2 * b + 1]);
            if (in) {
                int r = b * F_DIM + f;
                p.frow[r >> 5] |= 1u << (r & 31);
            }
        }

    // Time: (128, 10) draws, span 101, multiplier 2^32 % 101 = 68
    for (int j = 0; j < B_DIM * 10; j++) {
        uint32_t h  = rbits(k1t, (uint32_t)j);
        uint32_t l  = rbits(k2t, (uint32_t)j);
        uint32_t ub = rbits(kst, (uint32_t)j);
        uint32_t w  = ((h % 101u) * 68u + (l % 101u)) % 101u;
        float u  = (float)(ub >> 9) * (1.0f / 8388608.0f);
        int hi   = T_DIM - (int)w;                          // max(1,4000-w), w<=100
        int s    = (int)(u * (float)hi);
        p.ts[j] = (short)s;
        p.tw[j] = (uint8_t)w;
    }
}

} // namespace sa_host

// ============================ launch ======================================

extern "C" void kernel_launch(void* const* d_in, const int* in_sizes, int n_in,
                              void* d_out, int out_size) {
    (void)in_sizes; (void)n_in; (void)out_size;
    const float* x   = (const float*)d_in[0];
    float*       out = (float*)d_out;

    MaskParams p;
    sa_host::fill_params(p);

    apply_kernel<<<B_DIM * F_DIM, NTHREADS>>>(x, out, p);
}

// round 14
// speedup vs baseline: 1.0149x; 1.0085x over previous
#include <cuda_runtime.h>
#include <cstdint>
#include <cmath>

// ---------------------------------------------------------------------------
// SpecAugment: out = where(freq_mask[b,f] | time_mask[b,t], 0, x)
// FINAL (converged, frozen): host computes the 1280 threefry draws (bit-exact
// jax_threefry_partitionable reconstruction of jax.random.key(42) derivation,
// rel_err=0.0 across 12 benches), passed as a compact 5.1KB __grid_constant__
// param. Device: one row per 128-thread block (fine-grained => HW work-steal
// balances store-only freq-masked rows), Blackwell 256-bit vector ops
// (ld/st.global.v8.f32 -> LDG.256/STG.256): 4 x 32B chunks per thread,
// front-batched, loads skipped where fully masked, streaming stores.
// Performance: ~38us kernel @ ~5.6TB/s = DRAM mixed-stream ceiling for
// 164MB mandatory writes + ~51MB live reads. All structural levers probed
// (MLP, vector width, block size, rows/block, occupancy, cache policy,
// persistent layouts); differences are below run-to-run noise.
// ---------------------------------------------------------------------------

#define B_DIM 128
#define F_DIM 80
#define T_DIM 4000
#define T8    500           // 32B (8-float) chunks per row
#define TW    125           // 32-bit time-mask words per batch
#define NTHREADS 128
#define VEC 4               // chunks per thread (128 * 4 = 512 >= 500)

struct MaskParams {
    uint32_t frow[(B_DIM * F_DIM + 31) / 32];  // 1280B: bit per (b,f) row
    short    ts[B_DIM * 10];                   // 2560B: time band start
    uint8_t  tw[B_DIM * 10];                   // 1280B: time band width (<=100)
};

// ====================== 256-bit memory ops (sm_100a+) =====================

__device__ __forceinline__ void ld256_cs(const float* p, float* v) {
    asm volatile("ld.global.cs.v8.f32 {%0,%1,%2,%3,%4,%5,%6,%7}, [%8];"
        : "=f"(v[0]), "=f"(v[1]), "=f"(v[2]), "=f"(v[3]),
          "=f"(v[4]), "=f"(v[5]), "=f"(v[6]), "=f"(v[7])
        : "l"(p));
}

__device__ __forceinline__ void st256_cs(float* p, const float* v) {
    asm volatile("st.global.cs.v8.f32 [%0], {%1,%2,%3,%4,%5,%6,%7,%8};"
        :: "l"(p),
           "f"(v[0]), "f"(v[1]), "f"(v[2]), "f"(v[3]),
           "f"(v[4]), "f"(v[5]), "f"(v[6]), "f"(v[7])
        : "memory");
}

// ============================ device ======================================

__global__ void __launch_bounds__(NTHREADS)
apply_kernel(const float* __restrict__ x, float* __restrict__ out,
             const __grid_constant__ MaskParams p)
{
    const int row = blockIdx.x;                // row = b*80 + f (contiguous)
    const int b   = row / F_DIM;
    const int tid = threadIdx.x;

    const float* xr   = x   + (size_t)row * T_DIM;
    float*       orow = out + (size_t)row * T_DIM;

    float zv[8] = {0.f, 0.f, 0.f, 0.f, 0.f, 0.f, 0.f, 0.f};

    // Freq-masked row: store zeros, read nothing, exit fast (work-steal
    // backfills this SM slot with another block).
    if ((p.frow[row >> 5] >> (row & 31)) & 1u) {
#pragma unroll
        for (int i = 0; i < VEC; i++) {
            int t8 = tid + i * NTHREADS;
            if (t8 < T8) st256_cs(orow + t8 * 8, zv);
        }
        return;
    }

    // Build this batch's packed time mask in shared (125 words, 10 bands).
    __shared__ uint32_t s_tb[TW];
    if (tid < TW) {
        const int base = tid * 32;
        uint32_t word = 0u;
#pragma unroll
        for (int m = 0; m < 10; m++) {
            int s = p.ts[b * 10 + m];
            int e = s + (int)p.tw[b * 10 + m];
            int lo = s - base;  lo = lo < 0  ? 0  : lo;
            int hi = e - base;  hi = hi > 32 ? 32 : hi;
            if (hi > lo) {
                uint32_t mhi = (hi >= 32) ? 0xFFFFFFFFu : ((1u << hi) - 1u);
                word |= mhi & ~((1u << lo) - 1u);
            }
        }
        s_tb[tid] = word;
    }
    __syncthreads();

    // Per-chunk mask bytes: chunk t8 covers t in [8*t8, 8*t8+8) = byte
    // (t8 & 3) of time-mask word (t8 >> 2).
    uint32_t mb[VEC];
#pragma unroll
    for (int i = 0; i < VEC; i++) {
        int t8 = tid + i * NTHREADS;
        mb[i] = (t8 < T8) ? ((s_tb[t8 >> 2] >> ((t8 & 3) * 8)) & 0xFFu) : 0xFFu;
    }

    // ALL 256-bit loads front-batched; fully-masked chunks skipped.
    float v[VEC][8];
#pragma unroll
    for (int i = 0; i < VEC; i++) {
#pragma unroll
        for (int jj = 0; jj < 8; jj++) v[i][jj] = 0.f;
        int t8 = tid + i * NTHREADS;
        if (t8 < T8 && mb[i] != 0xFFu) ld256_cs(xr + t8 * 8, v[i]);
    }

    // Mask + 256-bit streaming stores.
#pragma unroll
    for (int i = 0; i < VEC; i++) {
        int t8 = tid + i * NTHREADS;
        if (t8 >= T8) continue;
#pragma unroll
        for (int jj = 0; jj < 8; jj++)
            v[i][jj] = ((mb[i] >> jj) & 1u) ? 0.f : v[i][jj];
        st256_cs(orow + t8 * 8, v[i]);
    }
}

// ============================ host: threefry draws ========================

namespace sa_host {

struct U2 { uint32_t a, b; };

static inline U2 tf(uint32_t k0, uint32_t k1, uint32_t x0, uint32_t x1) {
    const uint32_t ks2 = k0 ^ k1 ^ 0x1BD11BDAu;
    x0 += k0; x1 += k1;
#define RND(r) { x0 += x1; x1 = (x1 << (r)) | (x1 >> (32 - (r))); x1 ^= x0; }
    RND(13) RND(15) RND(26) RND(6)
    x0 += k1;  x1 += ks2 + 1u;
    RND(17) RND(29) RND(16) RND(24)
    x0 += ks2; x1 += k0 + 2u;
    RND(13) RND(15) RND(26) RND(6)
    x0 += k0;  x1 += k1 + 3u;
    RND(17) RND(29) RND(16) RND(24)
    x0 += k1;  x1 += ks2 + 4u;
    RND(13) RND(15) RND(26) RND(6)
    x0 += ks2; x1 += k0 + 5u;
#undef RND
    return U2{x0, x1};
}

// jax_threefry_partitionable = True (verified bit-exact)
static inline U2 split_a(U2 k) { return tf(k.a, k.b, 0u, 0u); }
static inline U2 split_b(U2 k) { return tf(k.a, k.b, 0u, 1u); }
static inline uint32_t rbits(U2 k, uint32_t j) {
    U2 o = tf(k.a, k.b, 0u, j);
    return o.a ^ o.b;
}

static void fill_params(MaskParams& p) {
    U2 key{0u, 42u};                       // jax.random.key(42)
    U2 kf  = split_a(key), kt  = split_b(key);
    U2 kwf = split_a(kf),  ksf = split_b(kf);
    U2 kwt = split_a(kt),  kst = split_b(kt);
    U2 k1f = split_a(kwf), k2f = split_b(kwf);
    U2 k1t = split_a(kwt), k2t = split_b(kwt);

    // Freq: (128, 2) draws, span 28, multiplier 2^32 % 28 = 4
    int fs[B_DIM * 2], fe[B_DIM * 2];
    for (int j = 0; j < B_DIM * 2; j++) {
        uint32_t h  = rbits(k1f, (uint32_t)j);
        uint32_t l  = rbits(k2f, (uint32_t)j);
        uint32_t ub = rbits(ksf, (uint32_t)j);
        uint32_t w  = ((h % 28u) * 4u + (l % 28u)) % 28u;
        float u  = (float)(ub >> 9) * (1.0f / 8388608.0f);  // exact [0,1)
        int hi   = F_DIM - (int)w;                          // max(1,80-w), w<=27
        int s    = (int)(u * (float)hi);
        fs[j] = s; fe[j] = s + (int)w;
    }
    for (int i = 0; i < (int)(sizeof(p.frow) / sizeof(p.frow[0])); i++) p.frow[i] = 0u;
    for (int b = 0; b < B_DIM; b++)
        for (int f = 0; f < F_DIM; f++) {
            bool in = (f >= fs[2 * b]     && f < fe[2 * b]) ||
                      (f >= fs[2 * b + 1] && f < fe[2 * b + 1]);
            if (in) {
                int r = b * F_DIM + f;
                p.frow[r >> 5] |= 1u << (r & 31);
            }
        }

    // Time: (128, 10) draws, span 101, multiplier 2^32 % 101 = 68
    for (int j = 0; j < B_DIM * 10; j++) {
        uint32_t h  = rbits(k1t, (uint32_t)j);
        uint32_t l  = rbits(k2t, (uint32_t)j);
        uint32_t ub = rbits(kst, (uint32_t)j);
        uint32_t w  = ((h % 101u) * 68u + (l % 101u)) % 101u;
        float u  = (float)(ub >> 9) * (1.0f / 8388608.0f);
        int hi   = T_DIM - (int)w;                          // max(1,4000-w), w<=100
        int s    = (int)(u * (float)hi);
        p.ts[j] = (short)s;
        p.tw[j] = (uint8_t)w;
    }
}

} // namespace sa_host

// ============================ launch ======================================

extern "C" void kernel_launch(void* const* d_in, const int* in_sizes, int n_in,
                              void* d_out, int out_size) {
    (void)in_sizes; (void)n_in; (void)out_size;
    const float* x   = (const float*)d_in[0];
    float*       out = (float*)d_out;

    MaskParams p;
    sa_host::fill_params(p);

    apply_kernel<<<B_DIM * F_DIM, NTHREADS>>>(x, out, p);
}